// round 11
// baseline (speedup 1.0000x reference)
#include <cuda_runtime.h>
#include <math.h>
#include <stdint.h>

#define Bsz 512
#define Fsz 128
#define Dsz 1024
#define MN (Bsz * Dsz)
#define TSPLIT 4
#define NCH 4              // attention chunks per batch

// ---------------- scratch (no allocs allowed -> __device__ globals) ----------
__device__ float g_tln[MN];
__device__ float g_q[MN];
__device__ float g_qp[MN];
__device__ float g_cb[Bsz];
__device__ float g_s[MN];
__device__ float g_attn[MN];
__device__ float g_aln[MN];
__device__ float g_part[(size_t)TSPLIT * MN];
__device__ float g_kwt[Dsz * Dsz];       // k_w transposed
__device__ float g_s2[(size_t)NCH * MN]; // attention chunk partials
__device__ float g_ml[Bsz * 2 * NCH];    // per-chunk (m, l)

// ---------------- helpers ----------------------------------------------------
__device__ __forceinline__ void mma16(float* c, const uint32_t* a, const uint32_t* b) {
    asm volatile(
        "mma.sync.aligned.m16n8k16.row.col.f32.bf16.bf16.f32 "
        "{%0,%1,%2,%3}, {%4,%5,%6,%7}, {%8,%9}, {%0,%1,%2,%3};"
        : "+f"(c[0]), "+f"(c[1]), "+f"(c[2]), "+f"(c[3])
        : "r"(a[0]), "r"(a[1]), "r"(a[2]), "r"(a[3]), "r"(b[0]), "r"(b[1]));
}
__device__ __forceinline__ void ldsm4(uint32_t& r0, uint32_t& r1, uint32_t& r2,
                                      uint32_t& r3, uint32_t a) {
    asm volatile("ldmatrix.sync.aligned.m8n8.x4.shared.b16 {%0,%1,%2,%3}, [%4];"
                 : "=r"(r0), "=r"(r1), "=r"(r2), "=r"(r3) : "r"(a));
}
// split float4 (4 consecutive k) into bf16x2 hi/lo plane words (k-pairs)
__device__ __forceinline__ void cvt_planes(float4 v, uint32_t& h0, uint32_t& h1,
                                           uint32_t& l0, uint32_t& l1) {
    const uint32_t bx = __float_as_uint(v.x), by = __float_as_uint(v.y);
    const uint32_t bz = __float_as_uint(v.z), bw = __float_as_uint(v.w);
    h0 = (by & 0xFFFF0000u) | (bx >> 16);
    h1 = (bw & 0xFFFF0000u) | (bz >> 16);
    const float lx = v.x - __uint_as_float(bx & 0xFFFF0000u);
    const float ly = v.y - __uint_as_float(by & 0xFFFF0000u);
    const float lz = v.z - __uint_as_float(bz & 0xFFFF0000u);
    const float lw = v.w - __uint_as_float(bw & 0xFFFF0000u);
    asm("cvt.rn.bf16x2.f32 %0, %1, %2;" : "=r"(l0) : "f"(ly), "f"(lx));
    asm("cvt.rn.bf16x2.f32 %0, %1, %2;" : "=r"(l1) : "f"(lw), "f"(lz));
}

// ---------------- 1024x1024 transpose (for k_w) ------------------------------
__global__ __launch_bounds__(256) void transp(const float* __restrict__ in,
                                              float* __restrict__ out) {
    __shared__ float t[32][33];
    int x = blockIdx.x * 32 + threadIdx.x;
    int y = blockIdx.y * 32 + threadIdx.y;
#pragma unroll
    for (int j = 0; j < 32; j += 8) t[threadIdx.y + j][threadIdx.x] = in[(size_t)(y + j) * Dsz + x];
    __syncthreads();
    x = blockIdx.y * 32 + threadIdx.x;
    y = blockIdx.x * 32 + threadIdx.y;
#pragma unroll
    for (int j = 0; j < 32; j += 8) out[(size_t)(y + j) * Dsz + x] = t[threadIdx.x][threadIdx.y + j];
}

// ---------------- row LayerNorm over D=1024 ----------------------------------
__global__ __launch_bounds__(256) void ln_rows(const float* __restrict__ X,
                                               float* __restrict__ Y,
                                               const float* __restrict__ gam,
                                               const float* __restrict__ bet) {
    __shared__ float red[2][8];
    const int row = blockIdx.x, tid = threadIdx.x;
    const int lane = tid & 31, w = tid >> 5;
    float4 x = *(const float4*)(X + (size_t)row * Dsz + tid * 4);
    float ps = x.x + x.y + x.z + x.w;
    float pq = x.x * x.x + x.y * x.y + x.z * x.z + x.w * x.w;
#pragma unroll
    for (int o = 16; o; o >>= 1) {
        ps += __shfl_xor_sync(0xffffffffu, ps, o);
        pq += __shfl_xor_sync(0xffffffffu, pq, o);
    }
    if (lane == 0) { red[0][w] = ps; red[1][w] = pq; }
    __syncthreads();
    float S = 0.f, Q = 0.f;
#pragma unroll
    for (int i = 0; i < 8; ++i) { S += red[0][i]; Q += red[1][i]; }
    const float mu = S * (1.0f / Dsz);
    const float rstd = rsqrtf(Q * (1.0f / Dsz) - mu * mu + 1e-5f);
    float4 g = *(const float4*)(gam + tid * 4);
    float4 b = *(const float4*)(bet + tid * 4);
    float4 o;
    o.x = (x.x - mu) * rstd * g.x + b.x;
    o.y = (x.y - mu) * rstd * g.y + b.y;
    o.z = (x.z - mu) * rstd * g.z + b.z;
    o.w = (x.w - mu) * rstd * g.w + b.w;
    *(float4*)(Y + (size_t)row * Dsz + tid * 4) = o;
}

// ---------------- mma.sync bf16-split GEMM with ldmatrix frag loads ---------
// C[m,n] = sum_k A[m,k] * W[n,k]. Tile 128x128, BK=32, split-K=4, 256 thr.
#define NP 20
#define AH(s) ((s) * 10240 + 0)
#define AL(s) ((s) * 10240 + 2560)
#define BHs(s) ((s) * 10240 + 5120)
#define BLs(s) ((s) * 10240 + 7680)
#define GM_SMEM (2 * 10240 * 4)  // 81920 B

__global__ __launch_bounds__(256) void gemm_m(const float* __restrict__ A,
                                              const float* __restrict__ W,
                                              float* __restrict__ P) {
    extern __shared__ uint32_t sm[];
    uint32_t sb;
    asm("{ .reg .u64 t; cvta.to.shared.u64 t, %1; cvt.u32.u64 %0, t; }"
        : "=r"(sb) : "l"(sm));
    const int tid = threadIdx.x, lane = tid & 31, wid = tid >> 5;
    const int bm = blockIdx.x, bn = blockIdx.y, ks = blockIdx.z;
    const int kbase = ks * (Dsz / TSPLIT);
    const int g = lane >> 2, t4 = lane & 3;
    const int wm = (wid & 1) * 64, wn = (wid >> 1) * 32;
    const int rsel = lane & 15, csel = (lane >> 4) * 4;  // ldmatrix lane addressing

    float acc[4][4][4];
#pragma unroll
    for (int mi = 0; mi < 4; ++mi)
#pragma unroll
        for (int ni = 0; ni < 4; ++ni)
#pragma unroll
            for (int r = 0; r < 4; ++r) acc[mi][ni][r] = 0.f;

    // ldmatrix byte offsets (within a plane)
    uint32_t aoff[4], boff[2];
#pragma unroll
    for (int mi = 0; mi < 4; ++mi) aoff[mi] = ((wm + mi * 16 + rsel) * NP + csel) * 4;
#pragma unroll
    for (int p = 0; p < 2; ++p) boff[p] = ((wn + p * 16 + rsel) * NP + csel) * 4;

    float4 pa[4], pb[4];
    const int fr = tid >> 3, fj = tid & 7;
    const int pw = fj * 2;

#pragma unroll
    for (int L = 0; L < 4; ++L) {
        pa[L] = *(const float4*)(A + (size_t)(bm * 128 + fr + L * 32) * Dsz + kbase + fj * 4);
        pb[L] = *(const float4*)(W + (size_t)(bn * 128 + fr + L * 32) * Dsz + kbase + fj * 4);
    }
#pragma unroll
    for (int L = 0; L < 4; ++L) {
        uint32_t h0, h1, l0, l1;
        const int off = (fr + L * 32) * NP + pw;
        cvt_planes(pa[L], h0, h1, l0, l1);
        *(uint2*)(sm + AH(0) + off) = make_uint2(h0, h1);
        *(uint2*)(sm + AL(0) + off) = make_uint2(l0, l1);
        cvt_planes(pb[L], h0, h1, l0, l1);
        *(uint2*)(sm + BHs(0) + off) = make_uint2(h0, h1);
        *(uint2*)(sm + BLs(0) + off) = make_uint2(l0, l1);
    }
    __syncthreads();

    for (int it = 0; it < 8; ++it) {
        const int s = it & 1;
        if (it + 1 < 8) {
            const int kb = kbase + (it + 1) * 32;
#pragma unroll
            for (int L = 0; L < 4; ++L) {
                pa[L] = *(const float4*)(A + (size_t)(bm * 128 + fr + L * 32) * Dsz + kb + fj * 4);
                pb[L] = *(const float4*)(W + (size_t)(bn * 128 + fr + L * 32) * Dsz + kb + fj * 4);
            }
        }
        const uint32_t ah_b = sb + AH(s) * 4, al_b = sb + AL(s) * 4;
        const uint32_t bh_b = sb + BHs(s) * 4, bl_b = sb + BLs(s) * 4;
#pragma unroll
        for (int kq = 0; kq < 2; ++kq) {
            const uint32_t kqb = kq * 32;  // 8 words = 32 bytes
            uint32_t ah[4][4], al[4][4], bh[4][2], bl[4][2];
#pragma unroll
            for (int mi = 0; mi < 4; ++mi) {
                ldsm4(ah[mi][0], ah[mi][1], ah[mi][2], ah[mi][3], ah_b + aoff[mi] + kqb);
                ldsm4(al[mi][0], al[mi][1], al[mi][2], al[mi][3], al_b + aoff[mi] + kqb);
            }
#pragma unroll
            for (int p = 0; p < 2; ++p) {
                uint32_t r0, r1, r2, r3;
                ldsm4(r0, r1, r2, r3, bh_b + boff[p] + kqb);
                bh[2 * p][0] = r0; bh[2 * p + 1][0] = r1;
                bh[2 * p][1] = r2; bh[2 * p + 1][1] = r3;
                ldsm4(r0, r1, r2, r3, bl_b + boff[p] + kqb);
                bl[2 * p][0] = r0; bl[2 * p + 1][0] = r1;
                bl[2 * p][1] = r2; bl[2 * p + 1][1] = r3;
            }
#pragma unroll
            for (int mi = 0; mi < 4; ++mi)
#pragma unroll
                for (int ni = 0; ni < 4; ++ni) {
                    mma16(acc[mi][ni], ah[mi], bh[ni]);
                    mma16(acc[mi][ni], al[mi], bh[ni]);
                    mma16(acc[mi][ni], ah[mi], bl[ni]);
                }
        }
        if (it + 1 < 8) {
            const int ns = (it + 1) & 1;
#pragma unroll
            for (int L = 0; L < 4; ++L) {
                uint32_t h0, h1, l0, l1;
                const int off = (fr + L * 32) * NP + pw;
                cvt_planes(pa[L], h0, h1, l0, l1);
                *(uint2*)(sm + AH(ns) + off) = make_uint2(h0, h1);
                *(uint2*)(sm + AL(ns) + off) = make_uint2(l0, l1);
                cvt_planes(pb[L], h0, h1, l0, l1);
                *(uint2*)(sm + BHs(ns) + off) = make_uint2(h0, h1);
                *(uint2*)(sm + BLs(ns) + off) = make_uint2(l0, l1);
            }
        }
        __syncthreads();
    }

    float* Pp = P + (size_t)ks * MN;
#pragma unroll
    for (int mi = 0; mi < 4; ++mi) {
        const int m0 = bm * 128 + wm + mi * 16 + g;
#pragma unroll
        for (int ni = 0; ni < 4; ++ni) {
            const int n = bn * 128 + wn + ni * 8 + 2 * t4;
            *(float2*)(Pp + (size_t)m0 * Dsz + n) =
                make_float2(acc[mi][ni][0], acc[mi][ni][1]);
            *(float2*)(Pp + (size_t)(m0 + 8) * Dsz + n) =
                make_float2(acc[mi][ni][2], acc[mi][ni][3]);
        }
    }
}

// ---------------- plain combine, 2 float4 per thread -------------------------
template <bool HAS_BIAS>
__global__ __launch_bounds__(256) void combine_k(const float* __restrict__ P,
                                                 const float* __restrict__ bias,
                                                 float* __restrict__ out) {
#pragma unroll
    for (int h = 0; h < 2; ++h) {
        const int idx = blockIdx.x * 512 + h * 256 + threadIdx.x;
        float4 s = make_float4(0.f, 0.f, 0.f, 0.f);
#pragma unroll
        for (int sl = 0; sl < TSPLIT; ++sl) {
            float4 v = ((const float4*)(P + (size_t)sl * MN))[idx];
            s.x += v.x; s.y += v.y; s.z += v.z; s.w += v.w;
        }
        if (HAS_BIAS) {
            float4 bv = *(const float4*)(bias + ((idx * 4) & (Dsz - 1)));
            s.x += bv.x; s.y += bv.y; s.z += bv.z; s.w += bv.w;
        }
        ((float4*)out)[idx] = s;
    }
}

// ---------------- combine q + bias, and cb[b] = q[b].k_b, one CTA per row ----
__global__ __launch_bounds__(256) void comb_q_cb(const float* __restrict__ P,
                                                 const float* __restrict__ bias,
                                                 const float* __restrict__ kb,
                                                 float* __restrict__ q,
                                                 float* __restrict__ cb) {
    __shared__ float red[8];
    const int row = blockIdx.x, tid = threadIdx.x;
    const int lane = tid & 31, w = tid >> 5;
    const size_t off = (size_t)row * Dsz + tid * 4;
    float4 s = *(const float4*)(bias + tid * 4);
#pragma unroll
    for (int sl = 0; sl < TSPLIT; ++sl) {
        float4 v = *(const float4*)(P + (size_t)sl * MN + off);
        s.x += v.x; s.y += v.y; s.z += v.z; s.w += v.w;
    }
    *(float4*)(q + off) = s;
    float4 c = *(const float4*)(kb + tid * 4);
    float p = s.x * c.x + s.y * c.y + s.z * c.z + s.w * c.w;
#pragma unroll
    for (int o = 16; o; o >>= 1) p += __shfl_xor_sync(0xffffffffu, p, o);
    if (lane == 0) red[w] = p;
    __syncthreads();
    if (tid == 0) {
        float t = 0.f;
#pragma unroll
        for (int i = 0; i < 8; ++i) t += red[i];
        cb[row] = t;
    }
}

// ---------------- combine + bias (+residual) + LayerNorm, one CTA per row ---
template <bool ADD_RES>
__global__ __launch_bounds__(256) void comb_ln(const float* __restrict__ P,
                                               const float* __restrict__ bias,
                                               const float* __restrict__ res,
                                               const float* __restrict__ gam,
                                               const float* __restrict__ bet,
                                               float* __restrict__ Y) {
    __shared__ float red[2][8];
    const int row = blockIdx.x, tid = threadIdx.x;
    const int lane = tid & 31, w = tid >> 5;
    const size_t off = (size_t)row * Dsz + tid * 4;
    float4 x = *(const float4*)(bias + tid * 4);
#pragma unroll
    for (int sl = 0; sl < TSPLIT; ++sl) {
        float4 v = *(const float4*)(P + (size_t)sl * MN + off);
        x.x += v.x; x.y += v.y; x.z += v.z; x.w += v.w;
    }
    if (ADD_RES) {
        float4 r = *(const float4*)(res + off);
        x.x += r.x; x.y += r.y; x.z += r.z; x.w += r.w;
    }
    float ps = x.x + x.y + x.z + x.w;
    float pq = x.x * x.x + x.y * x.y + x.z * x.z + x.w * x.w;
#pragma unroll
    for (int o = 16; o; o >>= 1) {
        ps += __shfl_xor_sync(0xffffffffu, ps, o);
        pq += __shfl_xor_sync(0xffffffffu, pq, o);
    }
    if (lane == 0) { red[0][w] = ps; red[1][w] = pq; }
    __syncthreads();
    float S = 0.f, Q = 0.f;
#pragma unroll
    for (int i = 0; i < 8; ++i) { S += red[0][i]; Q += red[1][i]; }
    const float mu = S * (1.0f / Dsz);
    const float rstd = rsqrtf(Q * (1.0f / Dsz) - mu * mu + 1e-5f);
    float4 g = *(const float4*)(gam + tid * 4);
    float4 b = *(const float4*)(bet + tid * 4);
    float4 o;
    o.x = (x.x - mu) * rstd * g.x + b.x;
    o.y = (x.y - mu) * rstd * g.y + b.y;
    o.z = (x.z - mu) * rstd * g.z + b.z;
    o.w = (x.w - mu) * rstd * g.w + b.w;
    *(float4*)(Y + off) = o;
}

// ---------------- fused attention: NCH CTAs/batch, 2 frames/iteration -------
__global__ __launch_bounds__(256) void attn_fused(const float* __restrict__ video,
                                                  const float* __restrict__ qp,
                                                  const float* __restrict__ cbv,
                                                  const float* __restrict__ gam,
                                                  const float* __restrict__ bet,
                                                  float* __restrict__ s2,
                                                  float* __restrict__ ml) {
    __shared__ float red[2][6][8];
    const int b = blockIdx.x, chunk = blockIdx.y, tid = threadIdx.x;
    const int lane = tid & 31, w = tid >> 5;
    const int d0 = tid * 4;
    const int FH = Fsz / NCH;
    float4 g4 = *(const float4*)(gam + d0);
    float4 b4 = *(const float4*)(bet + d0);
    float4 q4 = *(const float4*)(qp + (size_t)b * Dsz + d0);
    const float cbb = cbv[b];
    const float* base = video + (size_t)b * Fsz * Dsz + (size_t)chunk * FH * Dsz;

    float m = -1e30f, l = 0.f;
    float4 acc = make_float4(0.f, 0.f, 0.f, 0.f);
    float4 x0 = *(const float4*)(base + d0);
    float4 x1 = *(const float4*)(base + Dsz + d0);

    for (int f = 0; f < FH; f += 2) {
        float4 n0 = x0, n1 = x1;
        if (f + 2 < FH) {
            n0 = *(const float4*)(base + (size_t)(f + 2) * Dsz + d0);
            n1 = *(const float4*)(base + (size_t)(f + 3) * Dsz + d0);
        }
        const int p = (f >> 1) & 1;
        float s0 = x0.x + x0.y + x0.z + x0.w;
        float q0 = x0.x * x0.x + x0.y * x0.y + x0.z * x0.z + x0.w * x0.w;
        float s1 = x1.x + x1.y + x1.z + x1.w;
        float q1 = x1.x * x1.x + x1.y * x1.y + x1.z * x1.z + x1.w * x1.w;
#pragma unroll
        for (int o = 16; o; o >>= 1) {
            s0 += __shfl_xor_sync(0xffffffffu, s0, o);
            q0 += __shfl_xor_sync(0xffffffffu, q0, o);
            s1 += __shfl_xor_sync(0xffffffffu, s1, o);
            q1 += __shfl_xor_sync(0xffffffffu, q1, o);
        }
        if (lane == 0) {
            red[p][0][w] = s0; red[p][1][w] = q0;
            red[p][2][w] = s1; red[p][3][w] = q1;
        }
        __syncthreads();
        float S0 = 0.f, Q0 = 0.f, S1 = 0.f, Q1 = 0.f;
#pragma unroll
        for (int i = 0; i < 8; ++i) {
            S0 += red[p][0][i]; Q0 += red[p][1][i];
            S1 += red[p][2][i]; Q1 += red[p][3][i];
        }
        const float mu0 = S0 * (1.0f / Dsz);
        const float r0 = rsqrtf(Q0 * (1.0f / Dsz) - mu0 * mu0 + 1e-5f);
        const float mu1 = S1 * (1.0f / Dsz);
        const float r1 = rsqrtf(Q1 * (1.0f / Dsz) - mu1 * mu1 + 1e-5f);
        float4 ln0, ln1;
        ln0.x = (x0.x - mu0) * r0 * g4.x + b4.x;
        ln0.y = (x0.y - mu0) * r0 * g4.y + b4.y;
        ln0.z = (x0.z - mu0) * r0 * g4.z + b4.z;
        ln0.w = (x0.w - mu0) * r0 * g4.w + b4.w;
        ln1.x = (x1.x - mu1) * r1 * g4.x + b4.x;
        ln1.y = (x1.y - mu1) * r1 * g4.y + b4.y;
        ln1.z = (x1.z - mu1) * r1 * g4.z + b4.z;
        ln1.w = (x1.w - mu1) * r1 * g4.w + b4.w;
        float d0p = ln0.x * q4.x + ln0.y * q4.y + ln0.z * q4.z + ln0.w * q4.w;
        float d1p = ln1.x * q4.x + ln1.y * q4.y + ln1.z * q4.z + ln1.w * q4.w;
#pragma unroll
        for (int o = 16; o; o >>= 1) {
            d0p += __shfl_xor_sync(0xffffffffu, d0p, o);
            d1p += __shfl_xor_sync(0xffffffffu, d1p, o);
        }
        if (lane == 0) { red[p][4][w] = d0p; red[p][5][w] = d1p; }
        __syncthreads();
        float dt0 = 0.f, dt1 = 0.f;
#pragma unroll
        for (int i = 0; i < 8; ++i) { dt0 += red[p][4][i]; dt1 += red[p][5][i]; }
        const float lg0 = (dt0 + cbb) * 0.03125f;
        const float lg1 = (dt1 + cbb) * 0.03125f;
        const float mn = fmaxf(m, fmaxf(lg0, lg1));
        const float alpha = __expf(m - mn);
        const float p0 = __expf(lg0 - mn);
        const float p1 = __expf(lg1 - mn);
        l = l * alpha + p0 + p1;
        acc.x = acc.x * alpha + p0 * ln0.x + p1 * ln1.x;
        acc.y = acc.y * alpha + p0 * ln0.y + p1 * ln1.y;
        acc.z = acc.z * alpha + p0 * ln0.z + p1 * ln1.z;
        acc.w = acc.w * alpha + p0 * ln0.w + p1 * ln1.w;
        m = mn;
        x0 = n0; x1 = n1;
    }
    *(float4*)(s2 + (size_t)chunk * MN + (size_t)b * Dsz + d0) = acc;
    if (tid == 0) {
        ml[(b * NCH + chunk) * 2 + 0] = m;
        ml[(b * NCH + chunk) * 2 + 1] = l;
    }
}

// ---------------- merge NCH attention chunks ---------------------------------
__global__ __launch_bounds__(256) void attn_merge(const float* __restrict__ s2,
                                                  const float* __restrict__ ml,
                                                  float* __restrict__ s_out) {
    const int b = blockIdx.x, d0 = threadIdx.x * 4;
    float M = -1e30f;
#pragma unroll
    for (int c = 0; c < NCH; ++c) M = fmaxf(M, ml[(b * NCH + c) * 2]);
    float wts[NCH], L = 0.f;
#pragma unroll
    for (int c = 0; c < NCH; ++c) {
        wts[c] = __expf(ml[(b * NCH + c) * 2] - M);
        L += ml[(b * NCH + c) * 2 + 1] * wts[c];
    }
    const float inv = 1.0f / L;
    float4 o = make_float4(0.f, 0.f, 0.f, 0.f);
#pragma unroll
    for (int c = 0; c < NCH; ++c) {
        float4 a = *(const float4*)(s2 + (size_t)c * MN + (size_t)b * Dsz + d0);
        o.x += a.x * wts[c]; o.y += a.y * wts[c];
        o.z += a.z * wts[c]; o.w += a.w * wts[c];
    }
    *(float4*)(s_out + (size_t)b * Dsz + d0) =
        make_float4(o.x * inv, o.y * inv, o.z * inv, o.w * inv);
}

// ---------------- driver -----------------------------------------------------
extern "C" void kernel_launch(void* const* d_in, const int* in_sizes, int n_in,
                              void* d_out, int out_size) {
    (void)in_sizes; (void)n_in; (void)out_size;
    const float* text  = (const float*)d_in[0];
    const float* video = (const float*)d_in[1];
    const float* q_w   = (const float*)d_in[2];
    const float* k_w   = (const float*)d_in[3];
    const float* v_w   = (const float*)d_in[4];
    const float* out_w = (const float*)d_in[5];
    const float* lin_w = (const float*)d_in[6];
    const float* q_b   = (const float*)d_in[7];
    const float* k_b   = (const float*)d_in[8];
    const float* v_b   = (const float*)d_in[9];
    const float* out_b = (const float*)d_in[10];
    const float* lin_b = (const float*)d_in[11];
    const float* ln1_g = (const float*)d_in[12];
    const float* ln1_b = (const float*)d_in[13];
    const float* ln2_g = (const float*)d_in[14];
    const float* ln2_b = (const float*)d_in[15];
    const float* ln3_g = (const float*)d_in[16];
    const float* ln3_b = (const float*)d_in[17];
    float* out = (float*)d_out;

    float *tln, *q, *qp, *cb, *s, *attn, *aln, *part, *kwt, *s2, *ml;
    cudaGetSymbolAddress((void**)&tln,  g_tln);
    cudaGetSymbolAddress((void**)&q,    g_q);
    cudaGetSymbolAddress((void**)&qp,   g_qp);
    cudaGetSymbolAddress((void**)&cb,   g_cb);
    cudaGetSymbolAddress((void**)&s,    g_s);
    cudaGetSymbolAddress((void**)&attn, g_attn);
    cudaGetSymbolAddress((void**)&aln,  g_aln);
    cudaGetSymbolAddress((void**)&part, g_part);
    cudaGetSymbolAddress((void**)&kwt,  g_kwt);
    cudaGetSymbolAddress((void**)&s2,   g_s2);
    cudaGetSymbolAddress((void**)&ml,   g_ml);

    cudaFuncSetAttribute(gemm_m, cudaFuncAttributeMaxDynamicSharedMemorySize, GM_SMEM);

    const dim3 gg(4, 8, TSPLIT);
    const int c2grid = MN / 4 / 512;  // 256 blocks, 2 float4/thread

    // kwt = k_w.T  (independent; run first)
    transp<<<dim3(32, 32), dim3(32, 8)>>>(k_w, kwt);
    // t_ln = LN1(text)
    ln_rows<<<Bsz, 256>>>(text, tln, ln1_g, ln1_b);
    // q = t_ln @ q_w.T + q_b ; cb[b] = q[b].k_b (fused)
    gemm_m<<<gg, 256, GM_SMEM>>>(tln, q_w, part);
    comb_q_cb<<<Bsz, 256>>>(part, q_b, k_b, q, cb);
    // qp = q @ k_w = q @ kwt.T
    gemm_m<<<gg, 256, GM_SMEM>>>(q, kwt, part);
    combine_k<false><<<c2grid, 256>>>(part, nullptr, qp);
    // attention over LN1(video), NCH chunks per batch, then merge
    attn_fused<<<dim3(Bsz, NCH), 256>>>(video, qp, cb, ln1_g, ln1_b, s2, ml);
    attn_merge<<<Bsz, 256>>>(s2, ml, s);
    // attn = s @ v_w.T + v_b
    gemm_m<<<gg, 256, GM_SMEM>>>(s, v_w, part);
    combine_k<true><<<c2grid, 256>>>(part, v_b, attn);
    // aln = LN2(attn @ out_w.T + out_b)   (y never materialized)
    gemm_m<<<gg, 256, GM_SMEM>>>(attn, out_w, part);
    comb_ln<false><<<Bsz, 256>>>(part, out_b, nullptr, ln2_g, ln2_b, aln);
    // out = LN3(aln + aln @ lin_w.T + lin_b)   (z never materialized)
    gemm_m<<<gg, 256, GM_SMEM>>>(aln, lin_w, part);
    comb_ln<true><<<Bsz, 256>>>(part, lin_b, aln, ln3_g, ln3_b, out);
}

// round 14
// speedup vs baseline: 1.1568x; 1.1568x over previous
#include <cuda_runtime.h>
#include <math.h>
#include <stdint.h>

#define Bsz 512
#define Fsz 128
#define Dsz 1024
#define MN (Bsz * Dsz)
#define TSPLIT 4

// ---------------- scratch (no allocs allowed -> __device__ globals) ----------
__device__ float g_tln[MN];
__device__ float g_q[MN];
__device__ float g_qp[MN];
__device__ float g_cb[Bsz];
__device__ float g_s[MN];
__device__ float g_attn[MN];
__device__ float g_aln[MN];
__device__ float g_part[(size_t)TSPLIT * MN];
__device__ float g_kwt[Dsz * Dsz];       // k_w transposed

// ---------------- helpers ----------------------------------------------------
__device__ __forceinline__ void mma16(float* c, const uint32_t* a, const uint32_t* b) {
    asm volatile(
        "mma.sync.aligned.m16n8k16.row.col.f32.bf16.bf16.f32 "
        "{%0,%1,%2,%3}, {%4,%5,%6,%7}, {%8,%9}, {%0,%1,%2,%3};"
        : "+f"(c[0]), "+f"(c[1]), "+f"(c[2]), "+f"(c[3])
        : "r"(a[0]), "r"(a[1]), "r"(a[2]), "r"(a[3]), "r"(b[0]), "r"(b[1]));
}
__device__ __forceinline__ void ldsm4(uint32_t& r0, uint32_t& r1, uint32_t& r2,
                                      uint32_t& r3, uint32_t a) {
    asm volatile("ldmatrix.sync.aligned.m8n8.x4.shared.b16 {%0,%1,%2,%3}, [%4];"
                 : "=r"(r0), "=r"(r1), "=r"(r2), "=r"(r3) : "r"(a));
}
__device__ __forceinline__ void cvt_planes(float4 v, uint32_t& h0, uint32_t& h1,
                                           uint32_t& l0, uint32_t& l1) {
    const uint32_t bx = __float_as_uint(v.x), by = __float_as_uint(v.y);
    const uint32_t bz = __float_as_uint(v.z), bw = __float_as_uint(v.w);
    h0 = (by & 0xFFFF0000u) | (bx >> 16);
    h1 = (bw & 0xFFFF0000u) | (bz >> 16);
    const float lx = v.x - __uint_as_float(bx & 0xFFFF0000u);
    const float ly = v.y - __uint_as_float(by & 0xFFFF0000u);
    const float lz = v.z - __uint_as_float(bz & 0xFFFF0000u);
    const float lw = v.w - __uint_as_float(bw & 0xFFFF0000u);
    asm("cvt.rn.bf16x2.f32 %0, %1, %2;" : "=r"(l0) : "f"(ly), "f"(lx));
    asm("cvt.rn.bf16x2.f32 %0, %1, %2;" : "=r"(l1) : "f"(lw), "f"(lz));
}

// ---------------- 1024x1024 transpose (for k_w) ------------------------------
__global__ __launch_bounds__(256) void transp(const float* __restrict__ in,
                                              float* __restrict__ out) {
    __shared__ float t[32][33];
    int x = blockIdx.x * 32 + threadIdx.x;
    int y = blockIdx.y * 32 + threadIdx.y;
#pragma unroll
    for (int j = 0; j < 32; j += 8) t[threadIdx.y + j][threadIdx.x] = in[(size_t)(y + j) * Dsz + x];
    __syncthreads();
    x = blockIdx.y * 32 + threadIdx.x;
    y = blockIdx.x * 32 + threadIdx.y;
#pragma unroll
    for (int j = 0; j < 32; j += 8) out[(size_t)(y + j) * Dsz + x] = t[threadIdx.x][threadIdx.y + j];
}

// ---------------- row LayerNorm over D=1024 ----------------------------------
__global__ __launch_bounds__(256) void ln_rows(const float* __restrict__ X,
                                               float* __restrict__ Y,
                                               const float* __restrict__ gam,
                                               const float* __restrict__ bet) {
    __shared__ float red[2][8];
    const int row = blockIdx.x, tid = threadIdx.x;
    const int lane = tid & 31, w = tid >> 5;
    float4 x = *(const float4*)(X + (size_t)row * Dsz + tid * 4);
    float ps = x.x + x.y + x.z + x.w;
    float pq = x.x * x.x + x.y * x.y + x.z * x.z + x.w * x.w;
#pragma unroll
    for (int o = 16; o; o >>= 1) {
        ps += __shfl_xor_sync(0xffffffffu, ps, o);
        pq += __shfl_xor_sync(0xffffffffu, pq, o);
    }
    if (lane == 0) { red[0][w] = ps; red[1][w] = pq; }
    __syncthreads();
    float S = 0.f, Q = 0.f;
#pragma unroll
    for (int i = 0; i < 8; ++i) { S += red[0][i]; Q += red[1][i]; }
    const float mu = S * (1.0f / Dsz);
    const float rstd = rsqrtf(Q * (1.0f / Dsz) - mu * mu + 1e-5f);
    float4 g = *(const float4*)(gam + tid * 4);
    float4 b = *(const float4*)(bet + tid * 4);
    float4 o;
    o.x = (x.x - mu) * rstd * g.x + b.x;
    o.y = (x.y - mu) * rstd * g.y + b.y;
    o.z = (x.z - mu) * rstd * g.z + b.z;
    o.w = (x.w - mu) * rstd * g.w + b.w;
    *(float4*)(Y + (size_t)row * Dsz + tid * 4) = o;
}

// ---------------- mma.sync bf16-split GEMM with ldmatrix frag loads ---------
#define NP 20
#define AH(s) ((s) * 10240 + 0)
#define AL(s) ((s) * 10240 + 2560)
#define BHs(s) ((s) * 10240 + 5120)
#define BLs(s) ((s) * 10240 + 7680)
#define GM_SMEM (2 * 10240 * 4)  // 81920 B

__global__ __launch_bounds__(256) void gemm_m(const float* __restrict__ A,
                                              const float* __restrict__ W,
                                              float* __restrict__ P) {
    extern __shared__ uint32_t sm[];
    uint32_t sb;
    asm("{ .reg .u64 t; cvta.to.shared.u64 t, %1; cvt.u32.u64 %0, t; }"
        : "=r"(sb) : "l"(sm));
    const int tid = threadIdx.x, lane = tid & 31, wid = tid >> 5;
    const int bm = blockIdx.x, bn = blockIdx.y, ks = blockIdx.z;
    const int kbase = ks * (Dsz / TSPLIT);
    const int g = lane >> 2, t4 = lane & 3;
    const int wm = (wid & 1) * 64, wn = (wid >> 1) * 32;
    const int rsel = lane & 15, csel = (lane >> 4) * 4;

    float acc[4][4][4];
#pragma unroll
    for (int mi = 0; mi < 4; ++mi)
#pragma unroll
        for (int ni = 0; ni < 4; ++ni)
#pragma unroll
            for (int r = 0; r < 4; ++r) acc[mi][ni][r] = 0.f;

    uint32_t aoff[4], boff[2];
#pragma unroll
    for (int mi = 0; mi < 4; ++mi) aoff[mi] = ((wm + mi * 16 + rsel) * NP + csel) * 4;
#pragma unroll
    for (int p = 0; p < 2; ++p) boff[p] = ((wn + p * 16 + rsel) * NP + csel) * 4;

    float4 pa[4], pb[4];
    const int fr = tid >> 3, fj = tid & 7;
    const int pw = fj * 2;

#pragma unroll
    for (int L = 0; L < 4; ++L) {
        pa[L] = *(const float4*)(A + (size_t)(bm * 128 + fr + L * 32) * Dsz + kbase + fj * 4);
        pb[L] = *(const float4*)(W + (size_t)(bn * 128 + fr + L * 32) * Dsz + kbase + fj * 4);
    }
#pragma unroll
    for (int L = 0; L < 4; ++L) {
        uint32_t h0, h1, l0, l1;
        const int off = (fr + L * 32) * NP + pw;
        cvt_planes(pa[L], h0, h1, l0, l1);
        *(uint2*)(sm + AH(0) + off) = make_uint2(h0, h1);
        *(uint2*)(sm + AL(0) + off) = make_uint2(l0, l1);
        cvt_planes(pb[L], h0, h1, l0, l1);
        *(uint2*)(sm + BHs(0) + off) = make_uint2(h0, h1);
        *(uint2*)(sm + BLs(0) + off) = make_uint2(l0, l1);
    }
    __syncthreads();

    for (int it = 0; it < 8; ++it) {
        const int s = it & 1;
        if (it + 1 < 8) {
            const int kb = kbase + (it + 1) * 32;
#pragma unroll
            for (int L = 0; L < 4; ++L) {
                pa[L] = *(const float4*)(A + (size_t)(bm * 128 + fr + L * 32) * Dsz + kb + fj * 4);
                pb[L] = *(const float4*)(W + (size_t)(bn * 128 + fr + L * 32) * Dsz + kb + fj * 4);
            }
        }
        const uint32_t ah_b = sb + AH(s) * 4, al_b = sb + AL(s) * 4;
        const uint32_t bh_b = sb + BHs(s) * 4, bl_b = sb + BLs(s) * 4;
#pragma unroll
        for (int kq = 0; kq < 2; ++kq) {
            const uint32_t kqb = kq * 32;
            uint32_t ah[4][4], al[4][4], bh[4][2], bl[4][2];
#pragma unroll
            for (int mi = 0; mi < 4; ++mi) {
                ldsm4(ah[mi][0], ah[mi][1], ah[mi][2], ah[mi][3], ah_b + aoff[mi] + kqb);
                ldsm4(al[mi][0], al[mi][1], al[mi][2], al[mi][3], al_b + aoff[mi] + kqb);
            }
#pragma unroll
            for (int p = 0; p < 2; ++p) {
                uint32_t r0, r1, r2, r3;
                ldsm4(r0, r1, r2, r3, bh_b + boff[p] + kqb);
                bh[2 * p][0] = r0; bh[2 * p + 1][0] = r1;
                bh[2 * p][1] = r2; bh[2 * p + 1][1] = r3;
                ldsm4(r0, r1, r2, r3, bl_b + boff[p] + kqb);
                bl[2 * p][0] = r0; bl[2 * p + 1][0] = r1;
                bl[2 * p][1] = r2; bl[2 * p + 1][1] = r3;
            }
#pragma unroll
            for (int mi = 0; mi < 4; ++mi)
#pragma unroll
                for (int ni = 0; ni < 4; ++ni) {
                    mma16(acc[mi][ni], ah[mi], bh[ni]);
                    mma16(acc[mi][ni], al[mi], bh[ni]);
                    mma16(acc[mi][ni], ah[mi], bl[ni]);
                }
        }
        if (it + 1 < 8) {
            const int ns = (it + 1) & 1;
#pragma unroll
            for (int L = 0; L < 4; ++L) {
                uint32_t h0, h1, l0, l1;
                const int off = (fr + L * 32) * NP + pw;
                cvt_planes(pa[L], h0, h1, l0, l1);
                *(uint2*)(sm + AH(ns) + off) = make_uint2(h0, h1);
                *(uint2*)(sm + AL(ns) + off) = make_uint2(l0, l1);
                cvt_planes(pb[L], h0, h1, l0, l1);
                *(uint2*)(sm + BHs(ns) + off) = make_uint2(h0, h1);
                *(uint2*)(sm + BLs(ns) + off) = make_uint2(l0, l1);
            }
        }
        __syncthreads();
    }

    float* Pp = P + (size_t)ks * MN;
#pragma unroll
    for (int mi = 0; mi < 4; ++mi) {
        const int m0 = bm * 128 + wm + mi * 16 + g;
#pragma unroll
        for (int ni = 0; ni < 4; ++ni) {
            const int n = bn * 128 + wn + ni * 8 + 2 * t4;
            *(float2*)(Pp + (size_t)m0 * Dsz + n) =
                make_float2(acc[mi][ni][0], acc[mi][ni][1]);
            *(float2*)(Pp + (size_t)(m0 + 8) * Dsz + n) =
                make_float2(acc[mi][ni][2], acc[mi][ni][3]);
        }
    }
}

// ---------------- plain combine, 2 float4 per thread -------------------------
template <bool HAS_BIAS>
__global__ __launch_bounds__(256) void combine_k(const float* __restrict__ P,
                                                 const float* __restrict__ bias,
                                                 float* __restrict__ out) {
#pragma unroll
    for (int h = 0; h < 2; ++h) {
        const int idx = blockIdx.x * 512 + h * 256 + threadIdx.x;
        float4 s = make_float4(0.f, 0.f, 0.f, 0.f);
#pragma unroll
        for (int sl = 0; sl < TSPLIT; ++sl) {
            float4 v = ((const float4*)(P + (size_t)sl * MN))[idx];
            s.x += v.x; s.y += v.y; s.z += v.z; s.w += v.w;
        }
        if (HAS_BIAS) {
            float4 bv = *(const float4*)(bias + ((idx * 4) & (Dsz - 1)));
            s.x += bv.x; s.y += bv.y; s.z += bv.z; s.w += bv.w;
        }
        ((float4*)out)[idx] = s;
    }
}

// ---------------- combine q + bias, and cb[b] = q[b].k_b ---------------------
__global__ __launch_bounds__(256) void comb_q_cb(const float* __restrict__ P,
                                                 const float* __restrict__ bias,
                                                 const float* __restrict__ kb,
                                                 float* __restrict__ q,
                                                 float* __restrict__ cb) {
    __shared__ float red[8];
    const int row = blockIdx.x, tid = threadIdx.x;
    const int lane = tid & 31, w = tid >> 5;
    const size_t off = (size_t)row * Dsz + tid * 4;
    float4 s = *(const float4*)(bias + tid * 4);
#pragma unroll
    for (int sl = 0; sl < TSPLIT; ++sl) {
        float4 v = *(const float4*)(P + (size_t)sl * MN + off);
        s.x += v.x; s.y += v.y; s.z += v.z; s.w += v.w;
    }
    *(float4*)(q + off) = s;
    float4 c = *(const float4*)(kb + tid * 4);
    float p = s.x * c.x + s.y * c.y + s.z * c.z + s.w * c.w;
#pragma unroll
    for (int o = 16; o; o >>= 1) p += __shfl_xor_sync(0xffffffffu, p, o);
    if (lane == 0) red[w] = p;
    __syncthreads();
    if (tid == 0) {
        float t = 0.f;
#pragma unroll
        for (int i = 0; i < 8; ++i) t += red[i];
        cb[row] = t;
    }
}

// ---------------- combine + bias (+residual) + LayerNorm ---------------------
template <bool ADD_RES>
__global__ __launch_bounds__(256) void comb_ln(const float* __restrict__ P,
                                               const float* __restrict__ bias,
                                               const float* __restrict__ res,
                                               const float* __restrict__ gam,
                                               const float* __restrict__ bet,
                                               float* __restrict__ Y) {
    __shared__ float red[2][8];
    const int row = blockIdx.x, tid = threadIdx.x;
    const int lane = tid & 31, w = tid >> 5;
    const size_t off = (size_t)row * Dsz + tid * 4;
    float4 x = *(const float4*)(bias + tid * 4);
#pragma unroll
    for (int sl = 0; sl < TSPLIT; ++sl) {
        float4 v = *(const float4*)(P + (size_t)sl * MN + off);
        x.x += v.x; x.y += v.y; x.z += v.z; x.w += v.w;
    }
    if (ADD_RES) {
        float4 r = *(const float4*)(res + off);
        x.x += r.x; x.y += r.y; x.z += r.z; x.w += r.w;
    }
    float ps = x.x + x.y + x.z + x.w;
    float pq = x.x * x.x + x.y * x.y + x.z * x.z + x.w * x.w;
#pragma unroll
    for (int o = 16; o; o >>= 1) {
        ps += __shfl_xor_sync(0xffffffffu, ps, o);
        pq += __shfl_xor_sync(0xffffffffu, pq, o);
    }
    if (lane == 0) { red[0][w] = ps; red[1][w] = pq; }
    __syncthreads();
    float S = 0.f, Q = 0.f;
#pragma unroll
    for (int i = 0; i < 8; ++i) { S += red[0][i]; Q += red[1][i]; }
    const float mu = S * (1.0f / Dsz);
    const float rstd = rsqrtf(Q * (1.0f / Dsz) - mu * mu + 1e-5f);
    float4 g = *(const float4*)(gam + tid * 4);
    float4 b = *(const float4*)(bet + tid * 4);
    float4 o;
    o.x = (x.x - mu) * rstd * g.x + b.x;
    o.y = (x.y - mu) * rstd * g.y + b.y;
    o.z = (x.z - mu) * rstd * g.z + b.z;
    o.w = (x.w - mu) * rstd * g.w + b.w;
    *(float4*)(Y + off) = o;
}

// ---------------- attention: one warp = one frame, ZERO in-loop barriers ----
// Identity: with qg_d = qp_d*g_d, A = sum qp*g, C = sum qp*b:
//   logit_f = (rstd_f*dqx_f - rstd_f*mu_f*A + C + cb)/32,  dqx = sum qg_d x_d
//   sum_f p_f ln_d = g_d*(V_d - S1) + b_d*L,  V=sum p*rstd*x, S1=sum p*rstd*mu
// Each warp: 16 frames, lane holds 32 d-elements (d = j*128 + lane*4).
__global__ __launch_bounds__(256) void attn_warp(const float* __restrict__ video,
                                                 const float* __restrict__ qp,
                                                 const float* __restrict__ cbv,
                                                 const float* __restrict__ gam,
                                                 const float* __restrict__ bet,
                                                 float* __restrict__ s_out) {
    __shared__ float sv[8][1028];
    __shared__ float sml[8][3];
    const int b = blockIdx.x, tid = threadIdx.x;
    const int lane = tid & 31, w = tid >> 5;
    const float cbb = cbv[b];

    // per-warp: load qp, fold gamma; compute A, C
    float4 qg[8];
    float Ap = 0.f, Cp = 0.f;
#pragma unroll
    for (int j = 0; j < 8; ++j) {
        const int d = j * 128 + lane * 4;
        float4 qv = *(const float4*)(qp + (size_t)b * Dsz + d);
        float4 gv = *(const float4*)(gam + d);
        float4 bv = *(const float4*)(bet + d);
        qg[j].x = qv.x * gv.x; qg[j].y = qv.y * gv.y;
        qg[j].z = qv.z * gv.z; qg[j].w = qv.w * gv.w;
        Ap += qg[j].x + qg[j].y + qg[j].z + qg[j].w;
        Cp += qv.x * bv.x + qv.y * bv.y + qv.z * bv.z + qv.w * bv.w;
    }
#pragma unroll
    for (int o = 16; o; o >>= 1) {
        Ap += __shfl_xor_sync(0xffffffffu, Ap, o);
        Cp += __shfl_xor_sync(0xffffffffu, Cp, o);
    }

    const float* base = video + (size_t)b * Fsz * Dsz + (size_t)(w * 16) * Dsz;
    float4 xc[8];
#pragma unroll
    for (int j = 0; j < 8; ++j)
        xc[j] = *(const float4*)(base + j * 128 + lane * 4);

    float m = -1e30f, l = 0.f, s1 = 0.f;
    float4 vac[8];
#pragma unroll
    for (int j = 0; j < 8; ++j) vac[j] = make_float4(0.f, 0.f, 0.f, 0.f);

    for (int fi = 0; fi < 16; ++fi) {
        float4 xn[8];
        if (fi + 1 < 16) {
#pragma unroll
            for (int j = 0; j < 8; ++j)
                xn[j] = *(const float4*)(base + (size_t)(fi + 1) * Dsz + j * 128 + lane * 4);
        }
        float s = 0.f, sq = 0.f, dq = 0.f;
#pragma unroll
        for (int j = 0; j < 8; ++j) {
            s += xc[j].x + xc[j].y + xc[j].z + xc[j].w;
            sq += xc[j].x * xc[j].x + xc[j].y * xc[j].y
                + xc[j].z * xc[j].z + xc[j].w * xc[j].w;
            dq += qg[j].x * xc[j].x + qg[j].y * xc[j].y
                + qg[j].z * xc[j].z + qg[j].w * xc[j].w;
        }
#pragma unroll
        for (int o = 16; o; o >>= 1) {
            s  += __shfl_xor_sync(0xffffffffu, s, o);
            sq += __shfl_xor_sync(0xffffffffu, sq, o);
            dq += __shfl_xor_sync(0xffffffffu, dq, o);
        }
        const float mu = s * (1.0f / Dsz);
        const float rstd = rsqrtf(sq * (1.0f / Dsz) - mu * mu + 1e-5f);
        const float logit = ((dq - mu * Ap) * rstd + Cp + cbb) * 0.03125f;
        const float mn = fmaxf(m, logit);
        const float alpha = __expf(m - mn);
        const float p = __expf(logit - mn);
        const float pr = p * rstd;
        l = l * alpha + p;
        s1 = s1 * alpha + pr * mu;
#pragma unroll
        for (int j = 0; j < 8; ++j) {
            vac[j].x = vac[j].x * alpha + pr * xc[j].x;
            vac[j].y = vac[j].y * alpha + pr * xc[j].y;
            vac[j].z = vac[j].z * alpha + pr * xc[j].z;
            vac[j].w = vac[j].w * alpha + pr * xc[j].w;
        }
        m = mn;
#pragma unroll
        for (int j = 0; j < 8; ++j) xc[j] = xn[j];
    }
    // stash per-warp state
#pragma unroll
    for (int j = 0; j < 8; ++j)
        *(float4*)(&sv[w][j * 128 + lane * 4]) = vac[j];
    if (lane == 0) { sml[w][0] = m; sml[w][1] = s1; sml[w][2] = l; }
    __syncthreads();

    // merge 8 warps; thread t owns d = t*4
    const int d0 = tid * 4;
    float M = -1e30f;
#pragma unroll
    for (int ww = 0; ww < 8; ++ww) M = fmaxf(M, sml[ww][0]);
    float L = 0.f, S1 = 0.f;
    float4 V = make_float4(0.f, 0.f, 0.f, 0.f);
#pragma unroll
    for (int ww = 0; ww < 8; ++ww) {
        const float wt = __expf(sml[ww][0] - M);
        L += sml[ww][2] * wt;
        S1 += sml[ww][1] * wt;
        float4 v = *(const float4*)(&sv[ww][d0]);
        V.x += v.x * wt; V.y += v.y * wt; V.z += v.z * wt; V.w += v.w * wt;
    }
    const float inv = 1.0f / L;
    float4 g = *(const float4*)(gam + d0);
    float4 bb = *(const float4*)(bet + d0);
    float4 o;
    o.x = (g.x * (V.x - S1)) * inv + bb.x;
    o.y = (g.y * (V.y - S1)) * inv + bb.y;
    o.z = (g.z * (V.z - S1)) * inv + bb.z;
    o.w = (g.w * (V.w - S1)) * inv + bb.w;
    *(float4*)(s_out + (size_t)b * Dsz + d0) = o;
}

// ---------------- driver -----------------------------------------------------
extern "C" void kernel_launch(void* const* d_in, const int* in_sizes, int n_in,
                              void* d_out, int out_size) {
    (void)in_sizes; (void)n_in; (void)out_size;
    const float* text  = (const float*)d_in[0];
    const float* video = (const float*)d_in[1];
    const float* q_w   = (const float*)d_in[2];
    const float* k_w   = (const float*)d_in[3];
    const float* v_w   = (const float*)d_in[4];
    const float* out_w = (const float*)d_in[5];
    const float* lin_w = (const float*)d_in[6];
    const float* q_b   = (const float*)d_in[7];
    const float* k_b   = (const float*)d_in[8];
    const float* v_b   = (const float*)d_in[9];
    const float* out_b = (const float*)d_in[10];
    const float* lin_b = (const float*)d_in[11];
    const float* ln1_g = (const float*)d_in[12];
    const float* ln1_b = (const float*)d_in[13];
    const float* ln2_g = (const float*)d_in[14];
    const float* ln2_b = (const float*)d_in[15];
    const float* ln3_g = (const float*)d_in[16];
    const float* ln3_b = (const float*)d_in[17];
    float* out = (float*)d_out;

    float *tln, *q, *qp, *cb, *s, *attn, *aln, *part, *kwt;
    cudaGetSymbolAddress((void**)&tln,  g_tln);
    cudaGetSymbolAddress((void**)&q,    g_q);
    cudaGetSymbolAddress((void**)&qp,   g_qp);
    cudaGetSymbolAddress((void**)&cb,   g_cb);
    cudaGetSymbolAddress((void**)&s,    g_s);
    cudaGetSymbolAddress((void**)&attn, g_attn);
    cudaGetSymbolAddress((void**)&aln,  g_aln);
    cudaGetSymbolAddress((void**)&part, g_part);
    cudaGetSymbolAddress((void**)&kwt,  g_kwt);

    cudaFuncSetAttribute(gemm_m, cudaFuncAttributeMaxDynamicSharedMemorySize, GM_SMEM);

    const dim3 gg(4, 8, TSPLIT);
    const int c2grid = MN / 4 / 512;  // 256 blocks, 2 float4/thread

    // kwt = k_w.T  (independent; run first)
    transp<<<dim3(32, 32), dim3(32, 8)>>>(k_w, kwt);
    // t_ln = LN1(text)
    ln_rows<<<Bsz, 256>>>(text, tln, ln1_g, ln1_b);
    // q = t_ln @ q_w.T + q_b ; cb[b] = q[b].k_b (fused)
    gemm_m<<<gg, 256, GM_SMEM>>>(tln, q_w, part);
    comb_q_cb<<<Bsz, 256>>>(part, q_b, k_b, q, cb);
    // qp = q @ k_w = q @ kwt.T
    gemm_m<<<gg, 256, GM_SMEM>>>(q, kwt, part);
    combine_k<false><<<c2grid, 256>>>(part, nullptr, qp);
    // attention over LN1(video): barrier-free warp-per-frame, writes s directly
    attn_warp<<<Bsz, 256>>>(video, qp, cb, ln1_g, ln1_b, s);
    // attn = s @ v_w.T + v_b
    gemm_m<<<gg, 256, GM_SMEM>>>(s, v_w, part);
    combine_k<true><<<c2grid, 256>>>(part, v_b, attn);
    // aln = LN2(attn @ out_w.T + out_b)
    gemm_m<<<gg, 256, GM_SMEM>>>(attn, out_w, part);
    comb_ln<false><<<Bsz, 256>>>(part, out_b, nullptr, ln2_g, ln2_b, aln);
    // out = LN3(aln + aln @ lin_w.T + lin_b)
    gemm_m<<<gg, 256, GM_SMEM>>>(aln, lin_w, part);
    comb_ln<true><<<Bsz, 256>>>(part, lin_b, aln, ln3_g, ln3_b, out);
}